// round 14
// baseline (speedup 1.0000x reference)
#include <cuda_runtime.h>
#include <cuda_fp16.h>
#include <cstdint>

#define Bdim 32
#define Tdim 128
#define Zdim 100
#define Sdim 6
#define Hdim 64
#define F1 512
#define F2 128
#define ZB (Zdim * Bdim)          // 3200 sequences
#define NROWS (ZB * Tdim)         // 409600

// ---------------- device scratch ----------------
__device__ __align__(16) __half g_a[NROWS * Hdim];   // GRU outputs fp16, row-major tiles
__device__ __align__(16) __half g_w1h[F1 * Hdim];    // w1 [512][64] fp16
__device__ __align__(16) __half g_w2h[F2 * F1];      // w2 [128][512] fp16

// ---------------- helpers ----------------
__device__ __forceinline__ float sigmoid_fast(float v) {
    return __fdividef(1.0f, 1.0f + __expf(-v));
}
__device__ __forceinline__ float tanh_fast(float v) {
    float e = __expf(2.0f * v);
    return 1.0f - __fdividef(2.0f, e + 1.0f);
}
__device__ __forceinline__ uint32_t smem_u32(const void* p) {
    uint32_t a;
    asm("{ .reg .u64 t; cvta.to.shared.u64 t, %1; cvt.u32.u64 %0, t; }" : "=r"(a) : "l"(p));
    return a;
}
__device__ __forceinline__ void ldsm_x4(uint32_t* r, uint32_t addr) {
    asm volatile("ldmatrix.sync.aligned.m8n8.x4.shared.b16 {%0,%1,%2,%3}, [%4];"
                 : "=r"(r[0]), "=r"(r[1]), "=r"(r[2]), "=r"(r[3]) : "r"(addr));
}
__device__ __forceinline__ void ldsm_x2(uint32_t* r, uint32_t addr) {
    asm volatile("ldmatrix.sync.aligned.m8n8.x2.shared.b16 {%0,%1}, [%2];"
                 : "=r"(r[0]), "=r"(r[1]) : "r"(addr));
}
__device__ __forceinline__ void mma_fp16(float* d, const uint32_t* a, const uint32_t* b) {
    asm volatile("mma.sync.aligned.m16n8k16.row.col.f32.f16.f16.f32 "
                 "{%0,%1,%2,%3}, {%4,%5,%6,%7}, {%8,%9}, {%0,%1,%2,%3};"
                 : "+f"(d[0]), "+f"(d[1]), "+f"(d[2]), "+f"(d[3])
                 : "r"(a[0]), "r"(a[1]), "r"(a[2]), "r"(a[3]), "r"(b[0]), "r"(b[1]));
}
__device__ __forceinline__ uint32_t hpack(float x, float y) {
    __half2 t = __floats2half2_rn(x, y);
    return *(uint32_t*)&t;
}
__device__ __forceinline__ uint32_t hpackh(__half x, __half y) {
    return (uint32_t)*(unsigned short*)&x | ((uint32_t)*(unsigned short*)&y << 16);
}
__device__ __forceinline__ void cp_async16(uint32_t dst, const void* src) {
    asm volatile("cp.async.cg.shared.global [%0], [%1], 16;" :: "r"(dst), "l"(src));
}
#define CP_COMMIT() asm volatile("cp.async.commit_group;" ::: "memory")
#define CP_WAIT(n)  asm volatile("cp.async.wait_group %0;" :: "n"(n) : "memory")

// ---------------- tensor-core GRU v3: split accumulator chains ----------------
// CTA = one zone = 32 sequences. ah/al double-buffered (1 barrier/step),
// h in registers. Each gate's MMA chain split into parallel accumulators to
// shorten the per-step dependent-latency chain.
#define GOFF_WHH  0                      // half whh[192][72]        27648 B
#define GOFF_WIH  27648                  // half wih[192][24]         9216 B
#define GOFF_AH   36864                  // half ah[2][32][72]        9216 B
#define GOFF_AL   46080                  // half al[2][32][72]        9216 B
#define GOFF_XA   55296                  // half xa[2][32][24]        3072 B
#define GSM_TOTAL 58368
#define ABUF 4608                        // bytes per ah/al buffer

__global__ __launch_bounds__(256, 1) void gru_kernel(
    const float* __restrict__ x,
    const float* __restrict__ Wih,
    const float* __restrict__ Whh,
    const float* __restrict__ bihp,
    const float* __restrict__ bhhp,
    const float* __restrict__ w1,
    const float* __restrict__ w2)
{
    extern __shared__ char gsm[];
    __half* whh_s = (__half*)(gsm + GOFF_WHH);
    __half* wih_s = (__half*)(gsm + GOFF_WIH);
    __half* ah_s  = (__half*)(gsm + GOFF_AH);
    __half* al_s  = (__half*)(gsm + GOFF_AL);
    __half* xa_s  = (__half*)(gsm + GOFF_XA);

    const int tid = threadIdx.x;
    const int w = tid >> 5;
    const int lane = tid & 31;
    const int qp = lane & 3;
    const int qr = lane >> 2;
    const int zz = blockIdx.x;           // zone
    const int nseq0 = zz * 32;

    // ---- inlined weight prep for the MLP (grid-stride over 100 CTAs) ----
    {
        const int stride = gridDim.x * blockDim.x;
        for (int i = blockIdx.x * blockDim.x + tid; i < F1 * Hdim; i += stride)
            g_w1h[i] = __float2half(w1[i]);
        for (int i = blockIdx.x * blockDim.x + tid; i < F2 * F1; i += stride)
            g_w2h[i] = __float2half(w2[i]);
    }

    // ---- zero wih pad, both ah/al buffers ----
    for (int i = tid; i < 2304; i += 256) ((uint32_t*)(gsm + GOFF_WIH))[i] = 0u;
    for (int i = tid; i < 5376; i += 256) ((uint32_t*)(gsm + GOFF_AH))[i] = 0u;

    // ---- stage W_hh [192][64] -> fp16 stride 72 ----
    for (int i = tid; i < 192 * 64; i += 256)
        whh_s[(i >> 6) * 72 + (i & 63)] = __float2half(Whh[i]);
    __syncthreads();   // wih zero before writing data cols
    // ---- stage W_ih [192][6] -> fp16 stride 24 (cols 6..23 zero) ----
    for (int i = tid; i < 192 * 6; i += 256)
        wih_s[(i / 6) * 24 + (i % 6)] = __float2half(Wih[i]);
    // ---- stage x(t=0) into xa[0] ----
    const int q = tid / 6, s = tid - (tid / 6) * 6;   // valid for tid<192
    if (tid < 192)
        xa_s[q * 24 + s] = __float2half(x[((q * Tdim + 0) * Zdim + zz) * Sdim + s]);
    __syncthreads();

    // ---- register-resident B fragments ----
    const uint32_t uWhh = smem_u32(whh_s);
    const uint32_t uWih = smem_u32(wih_s);
    const int Lb = lane & 15;
    uint32_t Bhh[3][4][2], Bih[3][2];
#pragma unroll
    for (int g = 0; g < 3; g++) {
        const int ng = g * 64 + w * 8;
        uint32_t r4[4];
        ldsm_x4(r4, uWhh + (uint32_t)(ng + (lane & 7)) * 144 + (uint32_t)(lane >> 3) * 16);
        Bhh[g][0][0] = r4[0]; Bhh[g][0][1] = r4[1];
        Bhh[g][1][0] = r4[2]; Bhh[g][1][1] = r4[3];
        ldsm_x4(r4, uWhh + (uint32_t)(ng + (lane & 7)) * 144 + (uint32_t)(lane >> 3) * 16 + 64);
        Bhh[g][2][0] = r4[0]; Bhh[g][2][1] = r4[1];
        Bhh[g][3][0] = r4[2]; Bhh[g][3][1] = r4[3];
        ldsm_x2(Bih[g], uWih + (uint32_t)(ng + (Lb & 7)) * 48 + (uint32_t)(Lb >> 3) * 16);
    }

    // ---- per-lane biases ----
    const int cb = w * 8 + 2 * qp;       // h-col base for this lane
    const float brz0 = bihp[cb]       + bhhp[cb];
    const float brz1 = bihp[cb + 1]   + bhhp[cb + 1];
    const float bz0  = bihp[64 + cb]  + bhhp[64 + cb];
    const float bz1  = bihp[64 + cb + 1] + bhhp[64 + cb + 1];
    const float bin0 = bihp[128 + cb],     bin1 = bihp[128 + cb + 1];
    const float bhn0 = bhhp[128 + cb],     bhn1 = bhhp[128 + cb + 1];

    // ---- per-lane ldmatrix A addressing ----
    const int arow_lo = ((lane >> 3) & 1) * 8 + (lane & 7);
    const uint32_t acolb = (uint32_t)((lane >> 4) & 1) * 16;
    const uint32_t uAH = smem_u32(ah_s);
    const uint32_t uAL = smem_u32(al_s);
    const uint32_t uXA = smem_u32(xa_s);

    // ---- h state in registers (fp32): [mt][rr][col01] ----
    float hreg[2][2][2];
#pragma unroll
    for (int a = 0; a < 2; a++)
#pragma unroll
        for (int b = 0; b < 2; b++) { hreg[a][b][0] = 0.0f; hreg[a][b][1] = 0.0f; }

    for (int t = 0; t < Tdim; t++) {
        const int cur = t & 1;
        const uint32_t rdbuf = (uint32_t)(cur ^ 1) * ABUF;   // h(t-1) plane

        __syncthreads();   // cross-warp: step t-1 epilogue writes visible

        // ---- ldsm A fragments (h hi/lo from prev buffer, x) ----
        uint32_t Ahi[2][4][4], Alo[2][4][4], Ax[2][4];
#pragma unroll
        for (int mt = 0; mt < 2; mt++) {
            const uint32_t rb = (uint32_t)(mt * 16 + arow_lo);
#pragma unroll
            for (int kk = 0; kk < 4; kk++) {
                ldsm_x4(Ahi[mt][kk], uAH + rdbuf + rb * 144 + acolb + kk * 32);
                ldsm_x4(Alo[mt][kk], uAL + rdbuf + rb * 144 + acolb + kk * 32);
            }
            ldsm_x4(Ax[mt], uXA + (uint32_t)cur * 1536 + rb * 48 + acolb);
        }
        // prefetch x(t+1)
        float xvn = 0.0f;
        if (tid < 192 && t + 1 < Tdim)
            xvn = x[((q * Tdim + (t + 1)) * Zdim + zz) * Sdim + s];

#pragma unroll
        for (int mt = 0; mt < 2; mt++) {
            // split accumulator chains: each gate 2 parallel hi chains of 2;
            // n-gate lo correction in its own chain of 2+2.
            float DhA[3][4], DhB[3][4], DloA[4], DloB[4], Dg[3][4];
#pragma unroll
            for (int g = 0; g < 3; g++) {
#pragma unroll
                for (int p = 0; p < 4; p++) { DhA[g][p] = 0.0f; DhB[g][p] = 0.0f; Dg[g][p] = 0.0f; }
                mma_fp16(DhA[g], Ahi[mt][0], Bhh[g][0]);
                mma_fp16(DhB[g], Ahi[mt][1], Bhh[g][1]);
                mma_fp16(DhA[g], Ahi[mt][2], Bhh[g][2]);
                mma_fp16(DhB[g], Ahi[mt][3], Bhh[g][3]);
                mma_fp16(Dg[g], Ax[mt], Bih[g]);
            }
#pragma unroll
            for (int p = 0; p < 4; p++) { DloA[p] = 0.0f; DloB[p] = 0.0f; }
            mma_fp16(DloA, Alo[mt][0], Bhh[2][0]);
            mma_fp16(DloB, Alo[mt][1], Bhh[2][1]);
            mma_fp16(DloA, Alo[mt][2], Bhh[2][2]);
            mma_fp16(DloB, Alo[mt][3], Bhh[2][3]);

            // ---- epilogue: gates + h update (writes current buffer) ----
#pragma unroll
            for (int rr = 0; rr < 2; rr++) {
                const int seqr = mt * 16 + rr * 8 + qr;
                const int i0 = rr * 2, i1 = rr * 2 + 1;
                float gr0 = DhA[0][i0] + DhB[0][i0];
                float gr1 = DhA[0][i1] + DhB[0][i1];
                float gz0 = DhA[1][i0] + DhB[1][i0];
                float gz1 = DhA[1][i1] + DhB[1][i1];
                float gn0 = DhA[2][i0] + DhB[2][i0] + DloA[i0] + DloB[i0];
                float gn1 = DhA[2][i1] + DhB[2][i1] + DloA[i1] + DloB[i1];
                float r0 = sigmoid_fast(Dg[0][i0] + gr0 + brz0);
                float r1 = sigmoid_fast(Dg[0][i1] + gr1 + brz1);
                float z0 = sigmoid_fast(Dg[1][i0] + gz0 + bz0);
                float z1 = sigmoid_fast(Dg[1][i1] + gz1 + bz1);
                float nn0 = tanh_fast(Dg[2][i0] + bin0 + r0 * (gn0 + bhn0));
                float nn1 = tanh_fast(Dg[2][i1] + bin1 + r1 * (gn1 + bhn1));
                float hn0 = nn0 + z0 * (hreg[mt][rr][0] - nn0);
                float hn1 = nn1 + z1 * (hreg[mt][rr][1] - nn1);
                hreg[mt][rr][0] = hn0;
                hreg[mt][rr][1] = hn1;
                __half hi0 = __float2half(hn0), hi1 = __float2half(hn1);
                __half lo0 = __float2half(hn0 - __half2float(hi0));
                __half lo1 = __float2half(hn1 - __half2float(hi1));
                const uint32_t wo = (uint32_t)cur * ABUF + (uint32_t)(seqr * 144 + cb * 2);
                *(uint32_t*)((char*)ah_s + wo) = hpackh(hi0, hi1);
                *(uint32_t*)((char*)al_s + wo) = hpackh(lo0, lo1);
                *(uint32_t*)&g_a[(size_t)(nseq0 + seqr) * (Tdim * Hdim) + t * Hdim + cb]
                    = hpackh(hi0, hi1);
            }
        }
        // store x(t+1) into alternate buffer
        if (tid < 192 && t + 1 < Tdim)
            xa_s[(cur ^ 1) * 768 + q * 24 + s] = __float2half(xvn);
    }
}

// ---------------- tensor-core fused MLP v4: s-step software pipeline ----------------
// Per s: ldsm bf1(s+1) -> epi(s) -> L1(s+1) (WAR reuse of D1, no double buffer)
// -> L2(s). epi(s)'s D1 wait is covered by the 32 L2(s-1) MMAs issued after L1(s).
#define SA1 72
#define SW1 72
#define SW2 136
#define OFF_A1 0                   // 256 rows x 144 B = 36864
#define OFF_W1 36864               // 2 bufs x 18432
#define OFF_W2 73728               // 2 bufs x 34816
#define OFF_B1 143360
#define OFF_B2 145408
#define OFF_W3 145920
#define SM_TOTAL 146432

__global__ __launch_bounds__(256, 1) void mlp_kernel(
    const float* __restrict__ b1,
    const float* __restrict__ b2,
    const float* __restrict__ b3,
    const float* __restrict__ w3,
    float* __restrict__ out)
{
    extern __shared__ char sm[];
    const int tid = threadIdx.x;
    const int w = tid >> 5;          // 0..7, owns rows [w*32, w*32+32) of 256
    const int lane = tid & 31;
    const int qp = lane & 3;
    const int qr = lane >> 2;
    const int bid = blockIdx.x;
    const uint32_t smb = smem_u32(sm);

    float* b1s = (float*)(sm + OFF_B1);
    float* b2s = (float*)(sm + OFF_B2);
    float* w3s = (float*)(sm + OFF_W3);

    // ---- prologue: cp.async A tiles + W chunk 0, then scalars ----
    {
        const uint4* asrc = (const uint4*)(g_a + (size_t)bid * 2 * (Tdim * Hdim));
#pragma unroll
        for (int jj = 0; jj < 8; jj++) {
            int i = tid + 256 * jj;                  // 0..2047
            int r = i >> 3, c = i & 7;
            cp_async16(smb + OFF_A1 + r * (SA1 * 2) + c * 16, asrc + i);
        }
        const uint4* w1src = (const uint4*)g_w1h;    // chunk 0
#pragma unroll
        for (int jj = 0; jj < 4; jj++) {
            int i = tid + 256 * jj;                  // 0..1023
            int r = i >> 3, c = i & 7;
            cp_async16(smb + OFF_W1 + r * (SW1 * 2) + c * 16, w1src + i);
        }
#pragma unroll
        for (int jj = 0; jj < 8; jj++) {
            int i = tid + 256 * jj;                  // 0..2047
            int r = i >> 4, c = i & 15;
            cp_async16(smb + OFF_W2 + r * (SW2 * 2) + c * 16,
                       (const uint4*)(g_w2h + r * F1 + c * 8));
        }
        CP_COMMIT();
    }
    for (int i = tid; i < F1; i += 256) b1s[i] = b1[i];
    if (tid < F2) { b2s[tid] = b2[tid]; w3s[tid] = w3[tid]; }

    const int arow_lo = ((lane >> 3) & 1) * 8 + (lane & 7);
    const int acol = ((lane >> 4) & 1) * 8;
    const uint32_t uA1 = smb + OFF_A1 + ((w * 32 + arow_lo) * SA1 + acol) * 2;
    const uint32_t uW1x4 = smb + OFF_W1 + ((lane & 7) * SW1 + (lane >> 3) * 8) * 2;
    const uint32_t uW2x4 = smb + OFF_W2 +
        ((((lane >> 4) * 8 + (lane & 7)) * SW2) + ((lane >> 3) & 1) * 8) * 2;

    float D2[16][2][4];
#pragma unroll
    for (int jj = 0; jj < 16; jj++)
#pragma unroll
        for (int mh = 0; mh < 2; mh++)
#pragma unroll
            for (int p = 0; p < 4; p++) D2[jj][mh][p] = 0.0f;

    uint32_t Ah[2][4][4];
    bool a_loaded = false;

#pragma unroll 1
    for (int ch = 0; ch < 4; ch++) {
        const uint32_t wbuf = (uint32_t)(ch & 1);
        // ---- issue cp.async for chunk ch+1 into the alternate buffers ----
        if (ch + 1 < 4) {
            const uint32_t nb = (uint32_t)((ch + 1) & 1);
            const uint4* w1src = (const uint4*)(g_w1h + (ch + 1) * 128 * Hdim);
#pragma unroll
            for (int jj = 0; jj < 4; jj++) {
                int i = tid + 256 * jj;
                int r = i >> 3, c = i & 7;
                cp_async16(smb + OFF_W1 + nb * 18432 + r * (SW1 * 2) + c * 16, w1src + i);
            }
#pragma unroll
            for (int jj = 0; jj < 8; jj++) {
                int i = tid + 256 * jj;
                int r = i >> 4, c = i & 15;
                cp_async16(smb + OFF_W2 + nb * 34816 + r * (SW2 * 2) + c * 16,
                           (const uint4*)(g_w2h + r * F1 + (ch + 1) * 128 + c * 8));
            }
            CP_COMMIT();
            CP_WAIT(1);
        } else {
            CP_COMMIT();   // empty group keeps the count simple
            CP_WAIT(0);
        }
        __syncthreads();

        // ---- load A1 fragments once (after first arrival) ----
        if (!a_loaded) {
            a_loaded = true;
#pragma unroll
            for (int mh = 0; mh < 2; mh++)
#pragma unroll
                for (int kk = 0; kk < 4; kk++)
                    ldsm_x4(Ah[mh][kk], uA1 + mh * 16 * SA1 * 2 + kk * 32);
        }

        const uint32_t uW1c = uW1x4 + wbuf * 18432;
        const uint32_t uW2c = uW2x4 + wbuf * 34816;

        // ---- pipeline prologue: L1 for s=0 ----
        uint32_t bf1[2][8];
        float D1[2][2][4];
#pragma unroll
        for (int jj = 0; jj < 2; jj++) {
            const uint32_t bb = uW1c + jj * 8 * SW1 * 2;
            ldsm_x4(bf1[jj], bb);
            ldsm_x4(bf1[jj] + 4, bb + 64);
        }
#pragma unroll
        for (int jj = 0; jj < 2; jj++)
#pragma unroll
            for (int mh = 0; mh < 2; mh++) {
#pragma unroll
                for (int p = 0; p < 4; p++) D1[jj][mh][p] = 0.0f;
#pragma unroll
                for (int kk = 0; kk < 4; kk++)
                    mma_fp16(D1[jj][mh], Ah[mh][kk], bf1[jj] + 2 * kk);
            }

#pragma unroll 1
        for (int s = 0; s < 8; s++) {
            // ---- issue next s's W1 fragment loads (independent of D1) ----
            if (s < 7) {
#pragma unroll
                for (int jj = 0; jj < 2; jj++) {
                    const uint32_t bb = uW1c + (2 * (s + 1) + jj) * 8 * SW1 * 2;
                    ldsm_x4(bf1[jj], bb);
                    ldsm_x4(bf1[jj] + 4, bb + 64);
                }
            }
            // ---- epilogue(s): D1 wait covered by L2(s-1) MMAs ----
            uint32_t ahf[2][4];
#pragma unroll
            for (int jj = 0; jj < 2; jj++) {
                const int nb2 = ch * 128 + (2 * s + jj) * 8 + 2 * qp;
                const float bb0 = b1s[nb2], bb1 = b1s[nb2 + 1];
#pragma unroll
                for (int mh = 0; mh < 2; mh++) {
#pragma unroll
                    for (int pp = 0; pp < 2; pp++) {
                        float v0 = fmaxf(D1[jj][mh][2 * pp] + bb0, 0.0f);
                        float v1 = fmaxf(D1[jj][mh][2 * pp + 1] + bb1, 0.0f);
                        ahf[mh][jj * 2 + pp] = hpack(v0, v1);
                    }
                }
            }
            // ---- L1(s+1) into D1 (WAR reuse; keeps tensor pipe fed) ----
            if (s < 7) {
#pragma unroll
                for (int jj = 0; jj < 2; jj++)
#pragma unroll
                    for (int mh = 0; mh < 2; mh++) {
#pragma unroll
                        for (int p = 0; p < 4; p++) D1[jj][mh][p] = 0.0f;
#pragma unroll
                        for (int kk = 0; kk < 4; kk++)
                            mma_fp16(D1[jj][mh], Ah[mh][kk], bf1[jj] + 2 * kk);
                    }
            }
            // ---- L2(s): accumulate (k = ch*128 + s*16) ----
#pragma unroll
            for (int j2 = 0; j2 < 16; j2 += 2) {
                uint32_t bf[4];
                ldsm_x4(bf, uW2c + j2 * 8 * SW2 * 2 + s * 32);
                mma_fp16(D2[j2][0], ahf[0], bf);
                mma_fp16(D2[j2][1], ahf[1], bf);
                mma_fp16(D2[j2 + 1][0], ahf[0], bf + 2);
                mma_fp16(D2[j2 + 1][1], ahf[1], bf + 2);
            }
        }
        __syncthreads();   // all reads of wbuf done before it is refilled
    }

    // ---- layer3: out = relu(D2 + b2) . w3 + b3 ----
#pragma unroll
    for (int mh = 0; mh < 2; mh++) {
        float s0 = 0.0f, s1 = 0.0f;
#pragma unroll
        for (int j2 = 0; j2 < 16; j2++) {
            const int n2 = j2 * 8 + 2 * qp;
            const float w30 = w3s[n2], w31 = w3s[n2 + 1];
            const float bb0 = b2s[n2], bb1 = b2s[n2 + 1];
            s0 = fmaf(fmaxf(D2[j2][mh][0] + bb0, 0.0f), w30, s0);
            s0 = fmaf(fmaxf(D2[j2][mh][1] + bb1, 0.0f), w31, s0);
            s1 = fmaf(fmaxf(D2[j2][mh][2] + bb0, 0.0f), w30, s1);
            s1 = fmaf(fmaxf(D2[j2][mh][3] + bb1, 0.0f), w31, s1);
        }
        s0 += __shfl_xor_sync(0xffffffffu, s0, 1);
        s0 += __shfl_xor_sync(0xffffffffu, s0, 2);
        s1 += __shfl_xor_sync(0xffffffffu, s1, 1);
        s1 += __shfl_xor_sync(0xffffffffu, s1, 2);
        if (qp == 0) {
            const float bb = b3[0];
            const int row = bid * 256 + w * 32 + mh * 16 + qr;
            out[row] = s0 + bb;
            out[row + 8] = s1 + bb;
        }
    }
}

// ---------------- launch ----------------
extern "C" void kernel_launch(void* const* d_in, const int* in_sizes, int n_in,
                              void* d_out, int out_size) {
    const float* x    = (const float*)d_in[0];
    const float* W_ih = (const float*)d_in[1];
    const float* W_hh = (const float*)d_in[2];
    const float* b_ih = (const float*)d_in[3];
    const float* b_hh = (const float*)d_in[4];
    const float* w1   = (const float*)d_in[5];
    const float* b1   = (const float*)d_in[6];
    const float* w2   = (const float*)d_in[7];
    const float* b2   = (const float*)d_in[8];
    const float* w3   = (const float*)d_in[9];
    const float* b3   = (const float*)d_in[10];
    float* out = (float*)d_out;

    static int attr_set = 0;
    if (!attr_set) {
        cudaFuncSetAttribute(gru_kernel, cudaFuncAttributeMaxDynamicSharedMemorySize, GSM_TOTAL);
        cudaFuncSetAttribute(mlp_kernel, cudaFuncAttributeMaxDynamicSharedMemorySize, SM_TOTAL);
        attr_set = 1;
    }
    gru_kernel<<<Zdim, 256, GSM_TOTAL>>>(x, W_ih, W_hh, b_ih, b_hh, w1, w2);
    mlp_kernel<<<ZB / 2, 256, SM_TOTAL>>>(b1, b2, b3, w3, out);
}

// round 15
// speedup vs baseline: 1.0680x; 1.0680x over previous
#include <cuda_runtime.h>
#include <cuda_fp16.h>
#include <cstdint>

#define Bdim 32
#define Tdim 128
#define Zdim 100
#define Sdim 6
#define Hdim 64
#define F1 512
#define F2 128
#define ZB (Zdim * Bdim)          // 3200 sequences
#define NROWS (ZB * Tdim)         // 409600

// ---------------- device scratch ----------------
__device__ __align__(16) __half g_a[NROWS * Hdim];   // GRU outputs fp16, row-major tiles
__device__ __align__(16) __half g_w1h[F1 * Hdim];    // w1 [512][64] fp16
__device__ __align__(16) __half g_w2h[F2 * F1];      // w2 [128][512] fp16

// ---------------- helpers ----------------
// single-MUFU activations (MUFU.TANH): the GRU epilogue is MUFU-throughput-bound
__device__ __forceinline__ float tanh_mufu(float x) {
    float y; asm("tanh.approx.f32 %0, %1;" : "=f"(y) : "f"(x)); return y;
}
__device__ __forceinline__ float sigmoid_mufu(float v) {
    return fmaf(0.5f, tanh_mufu(0.5f * v), 0.5f);
}
__device__ __forceinline__ uint32_t smem_u32(const void* p) {
    uint32_t a;
    asm("{ .reg .u64 t; cvta.to.shared.u64 t, %1; cvt.u32.u64 %0, t; }" : "=r"(a) : "l"(p));
    return a;
}
__device__ __forceinline__ void ldsm_x4(uint32_t* r, uint32_t addr) {
    asm volatile("ldmatrix.sync.aligned.m8n8.x4.shared.b16 {%0,%1,%2,%3}, [%4];"
                 : "=r"(r[0]), "=r"(r[1]), "=r"(r[2]), "=r"(r[3]) : "r"(addr));
}
__device__ __forceinline__ void ldsm_x2(uint32_t* r, uint32_t addr) {
    asm volatile("ldmatrix.sync.aligned.m8n8.x2.shared.b16 {%0,%1}, [%2];"
                 : "=r"(r[0]), "=r"(r[1]) : "r"(addr));
}
__device__ __forceinline__ void mma_fp16(float* d, const uint32_t* a, const uint32_t* b) {
    asm volatile("mma.sync.aligned.m16n8k16.row.col.f32.f16.f16.f32 "
                 "{%0,%1,%2,%3}, {%4,%5,%6,%7}, {%8,%9}, {%0,%1,%2,%3};"
                 : "+f"(d[0]), "+f"(d[1]), "+f"(d[2]), "+f"(d[3])
                 : "r"(a[0]), "r"(a[1]), "r"(a[2]), "r"(a[3]), "r"(b[0]), "r"(b[1]));
}
__device__ __forceinline__ uint32_t hpack(float x, float y) {
    __half2 t = __floats2half2_rn(x, y);
    return *(uint32_t*)&t;
}
__device__ __forceinline__ uint32_t hpackh(__half x, __half y) {
    return (uint32_t)*(unsigned short*)&x | ((uint32_t)*(unsigned short*)&y << 16);
}
__device__ __forceinline__ void cp_async16(uint32_t dst, const void* src) {
    asm volatile("cp.async.cg.shared.global [%0], [%1], 16;" :: "r"(dst), "l"(src));
}
#define CP_COMMIT() asm volatile("cp.async.commit_group;" ::: "memory")
#define CP_WAIT(n)  asm volatile("cp.async.wait_group %0;" :: "n"(n) : "memory")

// ---------------- tensor-core GRU (r12 structure + MUFU.TANH activations) ----------------
// CTA = one zone = 32 sequences. h in smem fp32; A = h hi/lo fp16;
// lo-correction MMAs applied ONLY to the n-gate (first-order path).
#define GOFF_H    0                      // float h[32][66]           8448 B
#define GOFF_WHH  8448                   // half  whh[192][72]       27648 B
#define GOFF_WIH  36096                  // half  wih[192][24]        9216 B
#define GOFF_AH   45312                  // half  ah[32][72]          4608 B
#define GOFF_AL   49920                  // half  al[32][72]          4608 B
#define GOFF_XA   54528                  // half  xa[2][32][24]       3072 B
#define GSM_TOTAL 57600

__global__ __launch_bounds__(256, 1) void gru_kernel(
    const float* __restrict__ x,
    const float* __restrict__ Wih,
    const float* __restrict__ Whh,
    const float* __restrict__ bihp,
    const float* __restrict__ bhhp,
    const float* __restrict__ w1,
    const float* __restrict__ w2)
{
    extern __shared__ char gsm[];
    float* h_sh  = (float*)(gsm + GOFF_H);
    __half* whh_s = (__half*)(gsm + GOFF_WHH);
    __half* wih_s = (__half*)(gsm + GOFF_WIH);
    __half* ah_s  = (__half*)(gsm + GOFF_AH);
    __half* al_s  = (__half*)(gsm + GOFF_AL);
    __half* xa_s  = (__half*)(gsm + GOFF_XA);

    const int tid = threadIdx.x;
    const int w = tid >> 5;
    const int lane = tid & 31;
    const int qp = lane & 3;
    const int qr = lane >> 2;
    const int zz = blockIdx.x;           // zone
    const int nseq0 = zz * 32;

    // ---- inlined weight prep for the MLP (grid-stride over 100 CTAs) ----
    {
        const int stride = gridDim.x * blockDim.x;
        for (int i = blockIdx.x * blockDim.x + tid; i < F1 * Hdim; i += stride)
            g_w1h[i] = __float2half(w1[i]);
        for (int i = blockIdx.x * blockDim.x + tid; i < F2 * F1; i += stride)
            g_w2h[i] = __float2half(w2[i]);
    }

    // ---- zero h, wih pad, ah/al/xa ----
    for (int i = tid; i < 2112; i += 256) ((float*)(gsm + GOFF_H))[i] = 0.0f;
    for (int i = tid; i < 2304; i += 256) ((uint32_t*)(gsm + GOFF_WIH))[i] = 0u;
    for (int i = tid; i < 3072; i += 256) ((uint32_t*)(gsm + GOFF_AH))[i] = 0u;

    // ---- stage W_hh [192][64] -> fp16 stride 72 ----
    for (int i = tid; i < 192 * 64; i += 256)
        whh_s[(i >> 6) * 72 + (i & 63)] = __float2half(Whh[i]);
    __syncthreads();   // wih zero before writing data cols
    // ---- stage W_ih [192][6] -> fp16 stride 24 (cols 6..23 zero) ----
    for (int i = tid; i < 192 * 6; i += 256)
        wih_s[(i / 6) * 24 + (i % 6)] = __float2half(Wih[i]);
    // ---- stage x(t=0) into xa[0] ----
    const int q = tid / 6, s = tid - (tid / 6) * 6;   // valid for tid<192
    if (tid < 192)
        xa_s[q * 24 + s] = __float2half(x[((q * Tdim + 0) * Zdim + zz) * Sdim + s]);
    __syncthreads();

    // ---- register-resident B fragments ----
    const uint32_t uWhh = smem_u32(whh_s);
    const uint32_t uWih = smem_u32(wih_s);
    const int Lb = lane & 15;
    uint32_t Bhh[3][4][2], Bih[3][2];
#pragma unroll
    for (int g = 0; g < 3; g++) {
        const int ng = g * 64 + w * 8;
        uint32_t r4[4];
        ldsm_x4(r4, uWhh + (uint32_t)(ng + (lane & 7)) * 144 + (uint32_t)(lane >> 3) * 16);
        Bhh[g][0][0] = r4[0]; Bhh[g][0][1] = r4[1];
        Bhh[g][1][0] = r4[2]; Bhh[g][1][1] = r4[3];
        ldsm_x4(r4, uWhh + (uint32_t)(ng + (lane & 7)) * 144 + (uint32_t)(lane >> 3) * 16 + 64);
        Bhh[g][2][0] = r4[0]; Bhh[g][2][1] = r4[1];
        Bhh[g][3][0] = r4[2]; Bhh[g][3][1] = r4[3];
        ldsm_x2(Bih[g], uWih + (uint32_t)(ng + (Lb & 7)) * 48 + (uint32_t)(Lb >> 3) * 16);
    }

    // ---- per-lane biases ----
    const int cb = w * 8 + 2 * qp;       // h-col base for this lane
    const float brz0 = bihp[cb]       + bhhp[cb];
    const float brz1 = bihp[cb + 1]   + bhhp[cb + 1];
    const float bz0  = bihp[64 + cb]  + bhhp[64 + cb];
    const float bz1  = bihp[64 + cb + 1] + bhhp[64 + cb + 1];
    const float bin0 = bihp[128 + cb],     bin1 = bihp[128 + cb + 1];
    const float bhn0 = bhhp[128 + cb],     bhn1 = bhhp[128 + cb + 1];

    // ---- per-lane ldmatrix A addressing ----
    const int arow_lo = ((lane >> 3) & 1) * 8 + (lane & 7);
    const uint32_t acolb = (uint32_t)((lane >> 4) & 1) * 16;
    const uint32_t uAH = smem_u32(ah_s);
    const uint32_t uAL = smem_u32(al_s);
    const uint32_t uXA = smem_u32(xa_s);

    for (int t = 0; t < Tdim; t++) {
        const int cur = t & 1;

        // ---- ldsm A fragments (h hi/lo, x) ----
        uint32_t Ahi[2][4][4], Alo[2][4][4], Ax[2][4];
#pragma unroll
        for (int mt = 0; mt < 2; mt++) {
            const uint32_t rb = (uint32_t)(mt * 16 + arow_lo);
#pragma unroll
            for (int kk = 0; kk < 4; kk++) {
                ldsm_x4(Ahi[mt][kk], uAH + rb * 144 + acolb + kk * 32);
                ldsm_x4(Alo[mt][kk], uAL + rb * 144 + acolb + kk * 32);
            }
            ldsm_x4(Ax[mt], uXA + (uint32_t)cur * 1536 + rb * 48 + acolb);
        }
        // prefetch x(t+1)
        float xvn = 0.0f;
        if (tid < 192 && t + 1 < Tdim)
            xvn = x[((q * Tdim + (t + 1)) * Zdim + zz) * Sdim + s];
        __syncthreads();   // all ldsm reads done before epilogue writes

#pragma unroll
        for (int mt = 0; mt < 2; mt++) {
            float Dh[3][4], Dg[3][4];
#pragma unroll
            for (int g = 0; g < 3; g++) {
#pragma unroll
                for (int p = 0; p < 4; p++) { Dh[g][p] = 0.0f; Dg[g][p] = 0.0f; }
#pragma unroll
                for (int kk = 0; kk < 4; kk++) mma_fp16(Dh[g], Ahi[mt][kk], Bhh[g][kk]);
                mma_fp16(Dg[g], Ax[mt], Bih[g]);
            }
            // lo-correction only for n-gate (g=2)
#pragma unroll
            for (int kk = 0; kk < 4; kk++) mma_fp16(Dh[2], Alo[mt][kk], Bhh[2][kk]);

            // ---- epilogue: gates + h update (MUFU.TANH activations) ----
#pragma unroll
            for (int rr = 0; rr < 2; rr++) {
                const int seqr = mt * 16 + rr * 8 + qr;
                const int i0 = rr * 2, i1 = rr * 2 + 1;
                float r0 = sigmoid_mufu(Dg[0][i0] + Dh[0][i0] + brz0);
                float r1 = sigmoid_mufu(Dg[0][i1] + Dh[0][i1] + brz1);
                float z0 = sigmoid_mufu(Dg[1][i0] + Dh[1][i0] + bz0);
                float z1 = sigmoid_mufu(Dg[1][i1] + Dh[1][i1] + bz1);
                float nn0 = tanh_mufu(Dg[2][i0] + bin0 + r0 * (Dh[2][i0] + bhn0));
                float nn1 = tanh_mufu(Dg[2][i1] + bin1 + r1 * (Dh[2][i1] + bhn1));
                float h0 = h_sh[seqr * 66 + cb];
                float h1 = h_sh[seqr * 66 + cb + 1];
                float hn0 = nn0 + z0 * (h0 - nn0);
                float hn1 = nn1 + z1 * (h1 - nn1);
                h_sh[seqr * 66 + cb]     = hn0;
                h_sh[seqr * 66 + cb + 1] = hn1;
                __half hi0 = __float2half(hn0), hi1 = __float2half(hn1);
                __half lo0 = __float2half(hn0 - __half2float(hi0));
                __half lo1 = __float2half(hn1 - __half2float(hi1));
                *(uint32_t*)&ah_s[seqr * 72 + cb] = hpackh(hi0, hi1);
                *(uint32_t*)&al_s[seqr * 72 + cb] = hpackh(lo0, lo1);
                *(uint32_t*)&g_a[(size_t)(nseq0 + seqr) * (Tdim * Hdim) + t * Hdim + cb]
                    = hpackh(hi0, hi1);
            }
        }
        // store x(t+1) into alternate buffer
        if (tid < 192 && t + 1 < Tdim)
            xa_s[(cur ^ 1) * 768 + q * 24 + s] = __float2half(xvn);
        __syncthreads();
    }
}

// ---------------- tensor-core fused MLP v3 (exact r12): cp.async double-buffered W ----------------
#define SA1 72
#define SW1 72
#define SW2 136
#define OFF_A1 0                   // 256 rows x 144 B = 36864
#define OFF_W1 36864               // 2 bufs x 18432
#define OFF_W2 73728               // 2 bufs x 34816
#define OFF_B1 143360
#define OFF_B2 145408
#define OFF_W3 145920
#define SM_TOTAL 146432

__global__ __launch_bounds__(256, 1) void mlp_kernel(
    const float* __restrict__ b1,
    const float* __restrict__ b2,
    const float* __restrict__ b3,
    const float* __restrict__ w3,
    float* __restrict__ out)
{
    extern __shared__ char sm[];
    const int tid = threadIdx.x;
    const int w = tid >> 5;          // 0..7, owns rows [w*32, w*32+32) of 256
    const int lane = tid & 31;
    const int qp = lane & 3;
    const int qr = lane >> 2;
    const int bid = blockIdx.x;
    const uint32_t smb = smem_u32(sm);

    float* b1s = (float*)(sm + OFF_B1);
    float* b2s = (float*)(sm + OFF_B2);
    float* w3s = (float*)(sm + OFF_W3);

    // ---- prologue: cp.async A tiles + W chunk 0, then scalars ----
    {
        const uint4* asrc = (const uint4*)(g_a + (size_t)bid * 2 * (Tdim * Hdim));
#pragma unroll
        for (int jj = 0; jj < 8; jj++) {
            int i = tid + 256 * jj;                  // 0..2047
            int r = i >> 3, c = i & 7;
            cp_async16(smb + OFF_A1 + r * (SA1 * 2) + c * 16, asrc + i);
        }
        const uint4* w1src = (const uint4*)g_w1h;    // chunk 0
#pragma unroll
        for (int jj = 0; jj < 4; jj++) {
            int i = tid + 256 * jj;                  // 0..1023
            int r = i >> 3, c = i & 7;
            cp_async16(smb + OFF_W1 + r * (SW1 * 2) + c * 16, w1src + i);
        }
#pragma unroll
        for (int jj = 0; jj < 8; jj++) {
            int i = tid + 256 * jj;                  // 0..2047
            int r = i >> 4, c = i & 15;
            cp_async16(smb + OFF_W2 + r * (SW2 * 2) + c * 16,
                       (const uint4*)(g_w2h + r * F1 + c * 8));
        }
        CP_COMMIT();
    }
    for (int i = tid; i < F1; i += 256) b1s[i] = b1[i];
    if (tid < F2) { b2s[tid] = b2[tid]; w3s[tid] = w3[tid]; }

    const int arow_lo = ((lane >> 3) & 1) * 8 + (lane & 7);
    const int acol = ((lane >> 4) & 1) * 8;
    const uint32_t uA1 = smb + OFF_A1 + ((w * 32 + arow_lo) * SA1 + acol) * 2;
    const uint32_t uW1x4 = smb + OFF_W1 + ((lane & 7) * SW1 + (lane >> 3) * 8) * 2;
    const uint32_t uW2x4 = smb + OFF_W2 +
        ((((lane >> 4) * 8 + (lane & 7)) * SW2) + ((lane >> 3) & 1) * 8) * 2;

    float D2[16][2][4];
#pragma unroll
    for (int jj = 0; jj < 16; jj++)
#pragma unroll
        for (int mh = 0; mh < 2; mh++)
#pragma unroll
            for (int p = 0; p < 4; p++) D2[jj][mh][p] = 0.0f;

    uint32_t Ah[2][4][4];
    bool a_loaded = false;

#pragma unroll 1
    for (int ch = 0; ch < 4; ch++) {
        const uint32_t wbuf = (uint32_t)(ch & 1);
        // ---- issue cp.async for chunk ch+1 into the alternate buffers ----
        if (ch + 1 < 4) {
            const uint32_t nb = (uint32_t)((ch + 1) & 1);
            const uint4* w1src = (const uint4*)(g_w1h + (ch + 1) * 128 * Hdim);
#pragma unroll
            for (int jj = 0; jj < 4; jj++) {
                int i = tid + 256 * jj;
                int r = i >> 3, c = i & 7;
                cp_async16(smb + OFF_W1 + nb * 18432 + r * (SW1 * 2) + c * 16, w1src + i);
            }
#pragma unroll
            for (int jj = 0; jj < 8; jj++) {
                int i = tid + 256 * jj;
                int r = i >> 4, c = i & 15;
                cp_async16(smb + OFF_W2 + nb * 34816 + r * (SW2 * 2) + c * 16,
                           (const uint4*)(g_w2h + r * F1 + (ch + 1) * 128 + c * 8));
            }
            CP_COMMIT();
            CP_WAIT(1);
        } else {
            CP_COMMIT();   // empty group keeps the count simple
            CP_WAIT(0);
        }
        __syncthreads();

        // ---- load A1 fragments once (after first arrival) ----
        if (!a_loaded) {
            a_loaded = true;
#pragma unroll
            for (int mh = 0; mh < 2; mh++)
#pragma unroll
                for (int kk = 0; kk < 4; kk++)
                    ldsm_x4(Ah[mh][kk], uA1 + mh * 16 * SA1 * 2 + kk * 32);
        }

        const uint32_t uW1c = uW1x4 + wbuf * 18432;
        const uint32_t uW2c = uW2x4 + wbuf * 34816;

#pragma unroll 1
        for (int s = 0; s < 8; s++) {
            // ---- layer1: batch both n-tiles' W frags ----
            uint32_t bf1[2][8];
#pragma unroll
            for (int jj = 0; jj < 2; jj++) {
                const uint32_t bb = uW1c + (2 * s + jj) * 8 * SW1 * 2;
                ldsm_x4(bf1[jj], bb);
                ldsm_x4(bf1[jj] + 4, bb + 64);
            }
            float D1[2][2][4];
#pragma unroll
            for (int jj = 0; jj < 2; jj++)
#pragma unroll
                for (int mh = 0; mh < 2; mh++)
#pragma unroll
                    for (int p = 0; p < 4; p++) D1[jj][mh][p] = 0.0f;
#pragma unroll
            for (int jj = 0; jj < 2; jj++)
#pragma unroll
                for (int mh = 0; mh < 2; mh++)
#pragma unroll
                    for (int kk = 0; kk < 4; kk++)
                        mma_fp16(D1[jj][mh], Ah[mh][kk], bf1[jj] + 2 * kk);

            // ---- epilogue: relu(D1+b1) -> fp16 A2 fragments ----
            uint32_t ahf[2][4];
#pragma unroll
            for (int jj = 0; jj < 2; jj++) {
                const int nb2 = ch * 128 + (2 * s + jj) * 8 + 2 * qp;
                const float bb0 = b1s[nb2], bb1 = b1s[nb2 + 1];
#pragma unroll
                for (int mh = 0; mh < 2; mh++) {
#pragma unroll
                    for (int pp = 0; pp < 2; pp++) {
                        float v0 = fmaxf(D1[jj][mh][2 * pp] + bb0, 0.0f);
                        float v1 = fmaxf(D1[jj][mh][2 * pp + 1] + bb1, 0.0f);
                        ahf[mh][jj * 2 + pp] = hpack(v0, v1);
                    }
                }
            }
            // ---- layer2: accumulate (k = ch*128 + s*16) ----
#pragma unroll
            for (int j2 = 0; j2 < 16; j2 += 2) {
                uint32_t bf[4];
                ldsm_x4(bf, uW2c + j2 * 8 * SW2 * 2 + s * 32);
                mma_fp16(D2[j2][0], ahf[0], bf);
                mma_fp16(D2[j2][1], ahf[1], bf);
                mma_fp16(D2[j2 + 1][0], ahf[0], bf + 2);
                mma_fp16(D2[j2 + 1][1], ahf[1], bf + 2);
            }
        }
        __syncthreads();   // all reads of wbuf done before it is refilled
    }

    // ---- layer3: out = relu(D2 + b2) . w3 + b3 ----
#pragma unroll
    for (int mh = 0; mh < 2; mh++) {
        float s0 = 0.0f, s1 = 0.0f;
#pragma unroll
        for (int j2 = 0; j2 < 16; j2++) {
            const int n2 = j2 * 8 + 2 * qp;
            const float w30 = w3s[n2], w31 = w3s[n2 + 1];
            const float bb0 = b2s[n2], bb1 = b2s[n2 + 1];
            s0 = fmaf(fmaxf(D2[j2][mh][0] + bb0, 0.0f), w30, s0);
            s0 = fmaf(fmaxf(D2[j2][mh][1] + bb1, 0.0f), w31, s0);
            s1 = fmaf(fmaxf(D2[j2][mh][2] + bb0, 0.0f), w30, s1);
            s1 = fmaf(fmaxf(D2[j2][mh][3] + bb1, 0.0f), w31, s1);
        }
        s0 += __shfl_xor_sync(0xffffffffu, s0, 1);
        s0 += __shfl_xor_sync(0xffffffffu, s0, 2);
        s1 += __shfl_xor_sync(0xffffffffu, s1, 1);
        s1 += __shfl_xor_sync(0xffffffffu, s1, 2);
        if (qp == 0) {
            const float bb = b3[0];
            const int row = bid * 256 + w * 32 + mh * 16 + qr;
            out[row] = s0 + bb;
            out[row + 8] = s1 + bb;
        }
    }
}

// ---------------- launch ----------------
extern "C" void kernel_launch(void* const* d_in, const int* in_sizes, int n_in,
                              void* d_out, int out_size) {
    const float* x    = (const float*)d_in[0];
    const float* W_ih = (const float*)d_in[1];
    const float* W_hh = (const float*)d_in[2];
    const float* b_ih = (const float*)d_in[3];
    const float* b_hh = (const float*)d_in[4];
    const float* w1   = (const float*)d_in[5];
    const float* b1   = (const float*)d_in[6];
    const float* w2   = (const float*)d_in[7];
    const float* b2   = (const float*)d_in[8];
    const float* w3   = (const float*)d_in[9];
    const float* b3   = (const float*)d_in[10];
    float* out = (float*)d_out;

    static int attr_set = 0;
    if (!attr_set) {
        cudaFuncSetAttribute(gru_kernel, cudaFuncAttributeMaxDynamicSharedMemorySize, GSM_TOTAL);
        cudaFuncSetAttribute(mlp_kernel, cudaFuncAttributeMaxDynamicSharedMemorySize, SM_TOTAL);
        attr_set = 1;
    }
    gru_kernel<<<Zdim, 256, GSM_TOTAL>>>(x, W_ih, W_hh, b_ih, b_hh, w1, w2);
    mlp_kernel<<<ZB / 2, 256, SM_TOTAL>>>(b1, b2, b3, w3, out);
}

// round 16
// speedup vs baseline: 1.1249x; 1.0533x over previous
#include <cuda_runtime.h>
#include <cuda_fp16.h>
#include <cstdint>

#define Bdim 32
#define Tdim 128
#define Zdim 100
#define Sdim 6
#define Hdim 64
#define F1 512
#define F2 128
#define ZB (Zdim * Bdim)          // 3200 sequences
#define NROWS (ZB * Tdim)         // 409600

// ---------------- device scratch ----------------
__device__ __align__(16) __half g_a[NROWS * Hdim];   // GRU outputs fp16, row-major tiles
__device__ __align__(16) __half g_w1h[F1 * Hdim];    // w1 [512][64] fp16
__device__ __align__(16) __half g_w2h[F2 * F1];      // w2 [128][512] fp16

// ---------------- helpers ----------------
__device__ __forceinline__ float tanh_mufu(float x) {
    float y; asm("tanh.approx.f32 %0, %1;" : "=f"(y) : "f"(x)); return y;
}
__device__ __forceinline__ float sigmoid_mufu(float v) {
    return fmaf(0.5f, tanh_mufu(0.5f * v), 0.5f);
}
__device__ __forceinline__ uint32_t smem_u32(const void* p) {
    uint32_t a;
    asm("{ .reg .u64 t; cvta.to.shared.u64 t, %1; cvt.u32.u64 %0, t; }" : "=r"(a) : "l"(p));
    return a;
}
__device__ __forceinline__ void ldsm_x4(uint32_t* r, uint32_t addr) {
    asm volatile("ldmatrix.sync.aligned.m8n8.x4.shared.b16 {%0,%1,%2,%3}, [%4];"
                 : "=r"(r[0]), "=r"(r[1]), "=r"(r[2]), "=r"(r[3]) : "r"(addr));
}
__device__ __forceinline__ void ldsm_x2(uint32_t* r, uint32_t addr) {
    asm volatile("ldmatrix.sync.aligned.m8n8.x2.shared.b16 {%0,%1}, [%2];"
                 : "=r"(r[0]), "=r"(r[1]) : "r"(addr));
}
__device__ __forceinline__ void mma_fp16(float* d, const uint32_t* a, const uint32_t* b) {
    asm volatile("mma.sync.aligned.m16n8k16.row.col.f32.f16.f16.f32 "
                 "{%0,%1,%2,%3}, {%4,%5,%6,%7}, {%8,%9}, {%0,%1,%2,%3};"
                 : "+f"(d[0]), "+f"(d[1]), "+f"(d[2]), "+f"(d[3])
                 : "r"(a[0]), "r"(a[1]), "r"(a[2]), "r"(a[3]), "r"(b[0]), "r"(b[1]));
}
__device__ __forceinline__ uint32_t hpack(float x, float y) {
    __half2 t = __floats2half2_rn(x, y);
    return *(uint32_t*)&t;
}
__device__ __forceinline__ uint32_t hpackh(__half x, __half y) {
    return (uint32_t)*(unsigned short*)&x | ((uint32_t)*(unsigned short*)&y << 16);
}
__device__ __forceinline__ void cp_async16(uint32_t dst, const void* src) {
    asm volatile("cp.async.cg.shared.global [%0], [%1], 16;" :: "r"(dst), "l"(src));
}
#define CP_COMMIT() asm volatile("cp.async.commit_group;" ::: "memory")
#define CP_WAIT(n)  asm volatile("cp.async.wait_group %0;" :: "n"(n) : "memory")
#define BAR_GRP(id) asm volatile("bar.sync %0, 128;" :: "r"(id) : "memory")

// ---------------- tensor-core GRU v4: (mt, col-group) warp mapping ----------------
// CTA = one zone = 32 sequences. Warp (mt,cg) computes all 3 gates for h-cols
// [16cg,16cg+16) of rows [16mt,16mt+16): A-fragment crossbar traffic halved,
// row-halves fully decoupled via named group barriers.
#define GOFF_H    0                      // float h[32][66]           8448 B
#define GOFF_WHH  8448                   // half  whh[192][72]       27648 B
#define GOFF_WIH  36096                  // half  wih[192][24]        9216 B
#define GOFF_AH   45312                  // half  ah[32][72]          4608 B
#define GOFF_AL   49920                  // half  al[32][72]          4608 B
#define GOFF_XA   54528                  // half  xa[2][32][24]       3072 B
#define GSM_TOTAL 57600

__global__ __launch_bounds__(256, 1) void gru_kernel(
    const float* __restrict__ x,
    const float* __restrict__ Wih,
    const float* __restrict__ Whh,
    const float* __restrict__ bihp,
    const float* __restrict__ bhhp,
    const float* __restrict__ w1,
    const float* __restrict__ w2)
{
    extern __shared__ char gsm[];
    float* h_sh  = (float*)(gsm + GOFF_H);
    __half* whh_s = (__half*)(gsm + GOFF_WHH);
    __half* wih_s = (__half*)(gsm + GOFF_WIH);
    __half* ah_s  = (__half*)(gsm + GOFF_AH);
    __half* al_s  = (__half*)(gsm + GOFF_AL);
    __half* xa_s  = (__half*)(gsm + GOFF_XA);

    const int tid = threadIdx.x;
    const int w = tid >> 5;
    const int lane = tid & 31;
    const int qp = lane & 3;
    const int qr = lane >> 2;
    const int mt = w >> 2;               // row-half 0/1 (rows mt*16..mt*16+15)
    const int cg = w & 3;                // col-group (h-cols 16cg..16cg+15)
    const int zz = blockIdx.x;           // zone
    const int nseq0 = zz * 32;

    // ---- inlined weight prep for the MLP (grid-stride over 100 CTAs) ----
    {
        const int stride = gridDim.x * blockDim.x;
        for (int i = blockIdx.x * blockDim.x + tid; i < F1 * Hdim; i += stride)
            g_w1h[i] = __float2half(w1[i]);
        for (int i = blockIdx.x * blockDim.x + tid; i < F2 * F1; i += stride)
            g_w2h[i] = __float2half(w2[i]);
    }

    // ---- zero h, wih pad, ah/al/xa ----
    for (int i = tid; i < 2112; i += 256) ((float*)(gsm + GOFF_H))[i] = 0.0f;
    for (int i = tid; i < 2304; i += 256) ((uint32_t*)(gsm + GOFF_WIH))[i] = 0u;
    for (int i = tid; i < 3072; i += 256) ((uint32_t*)(gsm + GOFF_AH))[i] = 0u;

    // ---- stage W_hh [192][64] -> fp16 stride 72 ----
    for (int i = tid; i < 192 * 64; i += 256)
        whh_s[(i >> 6) * 72 + (i & 63)] = __float2half(Whh[i]);
    __syncthreads();   // wih zero before writing data cols
    // ---- stage W_ih [192][6] -> fp16 stride 24 (cols 6..23 zero) ----
    for (int i = tid; i < 192 * 6; i += 256)
        wih_s[(i / 6) * 24 + (i % 6)] = __float2half(Wih[i]);
    // ---- stage x(t=0) into xa[0] (full-block mapping, pre-loop) ----
    if (tid < 192) {
        int q0 = tid / 6, s0 = tid % 6;
        xa_s[q0 * 24 + s0] = __float2half(x[((q0 * Tdim + 0) * Zdim + zz) * Sdim + s0]);
    }
    __syncthreads();

    // ---- register-resident B fragments: 2 sub-tiles per gate ----
    const uint32_t uWhh = smem_u32(whh_s);
    const uint32_t uWih = smem_u32(wih_s);
    const int Lb = lane & 15;
    uint32_t Bhh[3][2][4][2], Bih[3][2][2];
#pragma unroll
    for (int g = 0; g < 3; g++) {
#pragma unroll
        for (int st = 0; st < 2; st++) {
            const int ng = g * 64 + (cg * 2 + st) * 8;
            uint32_t r4[4];
            ldsm_x4(r4, uWhh + (uint32_t)(ng + (lane & 7)) * 144 + (uint32_t)(lane >> 3) * 16);
            Bhh[g][st][0][0] = r4[0]; Bhh[g][st][0][1] = r4[1];
            Bhh[g][st][1][0] = r4[2]; Bhh[g][st][1][1] = r4[3];
            ldsm_x4(r4, uWhh + (uint32_t)(ng + (lane & 7)) * 144 + (uint32_t)(lane >> 3) * 16 + 64);
            Bhh[g][st][2][0] = r4[0]; Bhh[g][st][2][1] = r4[1];
            Bhh[g][st][3][0] = r4[2]; Bhh[g][st][3][1] = r4[3];
            ldsm_x2(Bih[g][st], uWih + (uint32_t)(ng + (Lb & 7)) * 48 + (uint32_t)(Lb >> 3) * 16);
        }
    }

    // ---- per-lane biases (two col sub-tiles) ----
    float brz[2][2], bz[2][2], bin[2][2], bhn[2][2];
    int cbase[2];
#pragma unroll
    for (int st = 0; st < 2; st++) {
        const int c = cg * 16 + st * 8 + 2 * qp;
        cbase[st] = c;
        brz[st][0] = bihp[c] + bhhp[c];
        brz[st][1] = bihp[c + 1] + bhhp[c + 1];
        bz[st][0]  = bihp[64 + c] + bhhp[64 + c];
        bz[st][1]  = bihp[64 + c + 1] + bhhp[64 + c + 1];
        bin[st][0] = bihp[128 + c];     bin[st][1] = bihp[128 + c + 1];
        bhn[st][0] = bhhp[128 + c];     bhn[st][1] = bhhp[128 + c + 1];
    }

    // ---- per-lane ldmatrix A addressing (own row-half only) ----
    const int arow = mt * 16 + ((lane >> 3) & 1) * 8 + (lane & 7);
    const uint32_t acolb = (uint32_t)((lane >> 4) & 1) * 16;
    const uint32_t uAH = smem_u32(ah_s);
    const uint32_t uAL = smem_u32(al_s);
    const uint32_t uXA = smem_u32(xa_s);
    const int barid = mt + 1;

    // group-local x loader mapping (16 seqs per group, 96 of 128 threads)
    const int lt = tid & 127;
    const int qx = mt * 16 + lt / 6, sx = lt % 6;
    const bool xload = (lt < 96);

    for (int t = 0; t < Tdim; t++) {
        const int cur = t & 1;

        // ---- ldsm A fragments (rows of own half; hi/lo + x) ----
        uint32_t Ahi[4][4], Alo[4][4], Ax[4];
#pragma unroll
        for (int kk = 0; kk < 4; kk++) {
            ldsm_x4(Ahi[kk], uAH + (uint32_t)arow * 144 + acolb + kk * 32);
            ldsm_x4(Alo[kk], uAL + (uint32_t)arow * 144 + acolb + kk * 32);
        }
        ldsm_x4(Ax, uXA + (uint32_t)cur * 1536 + (uint32_t)arow * 48 + acolb);
        // prefetch x(t+1) (group-local)
        float xvn = 0.0f;
        if (xload && t + 1 < Tdim)
            xvn = x[((qx * Tdim + (t + 1)) * Zdim + zz) * Sdim + sx];
        BAR_GRP(barid);   // group's ldsm reads done before epilogue writes

        float Dh[3][2][4], Dg[3][2][4];
#pragma unroll
        for (int g = 0; g < 3; g++) {
#pragma unroll
            for (int st = 0; st < 2; st++) {
#pragma unroll
                for (int p = 0; p < 4; p++) { Dh[g][st][p] = 0.0f; Dg[g][st][p] = 0.0f; }
#pragma unroll
                for (int kk = 0; kk < 4; kk++) mma_fp16(Dh[g][st], Ahi[kk], Bhh[g][st][kk]);
                mma_fp16(Dg[g][st], Ax, Bih[g][st]);
            }
        }
        // lo-correction only for n-gate (g=2)
#pragma unroll
        for (int st = 0; st < 2; st++)
#pragma unroll
            for (int kk = 0; kk < 4; kk++) mma_fp16(Dh[2][st], Alo[kk], Bhh[2][st][kk]);

        // ---- epilogue: gates + h update ----
#pragma unroll
        for (int st = 0; st < 2; st++) {
            const int c = cbase[st];
#pragma unroll
            for (int rr = 0; rr < 2; rr++) {
                const int seqr = mt * 16 + rr * 8 + qr;
                const int i0 = rr * 2, i1 = rr * 2 + 1;
                float r0 = sigmoid_mufu(Dg[0][st][i0] + Dh[0][st][i0] + brz[st][0]);
                float r1 = sigmoid_mufu(Dg[0][st][i1] + Dh[0][st][i1] + brz[st][1]);
                float z0 = sigmoid_mufu(Dg[1][st][i0] + Dh[1][st][i0] + bz[st][0]);
                float z1 = sigmoid_mufu(Dg[1][st][i1] + Dh[1][st][i1] + bz[st][1]);
                float nn0 = tanh_mufu(Dg[2][st][i0] + bin[st][0] + r0 * (Dh[2][st][i0] + bhn[st][0]));
                float nn1 = tanh_mufu(Dg[2][st][i1] + bin[st][1] + r1 * (Dh[2][st][i1] + bhn[st][1]));
                float h0 = h_sh[seqr * 66 + c];
                float h1 = h_sh[seqr * 66 + c + 1];
                float hn0 = nn0 + z0 * (h0 - nn0);
                float hn1 = nn1 + z1 * (h1 - nn1);
                h_sh[seqr * 66 + c]     = hn0;
                h_sh[seqr * 66 + c + 1] = hn1;
                __half hi0 = __float2half(hn0), hi1 = __float2half(hn1);
                __half lo0 = __float2half(hn0 - __half2float(hi0));
                __half lo1 = __float2half(hn1 - __half2float(hi1));
                *(uint32_t*)&ah_s[seqr * 72 + c] = hpackh(hi0, hi1);
                *(uint32_t*)&al_s[seqr * 72 + c] = hpackh(lo0, lo1);
                *(uint32_t*)&g_a[(size_t)(nseq0 + seqr) * (Tdim * Hdim) + t * Hdim + c]
                    = hpackh(hi0, hi1);
            }
        }
        // store x(t+1) into alternate buffer (group-local rows)
        if (xload && t + 1 < Tdim)
            xa_s[(cur ^ 1) * 768 + qx * 24 + sx] = __float2half(xvn);
        BAR_GRP(barid);   // group's writes done before next step's reads
    }
}

// ---------------- tensor-core fused MLP v3 (exact r12/r15): cp.async double-buffered W ----------------
#define SA1 72
#define SW1 72
#define SW2 136
#define OFF_A1 0                   // 256 rows x 144 B = 36864
#define OFF_W1 36864               // 2 bufs x 18432
#define OFF_W2 73728               // 2 bufs x 34816
#define OFF_B1 143360
#define OFF_B2 145408
#define OFF_W3 145920
#define SM_TOTAL 146432

__global__ __launch_bounds__(256, 1) void mlp_kernel(
    const float* __restrict__ b1,
    const float* __restrict__ b2,
    const float* __restrict__ b3,
    const float* __restrict__ w3,
    float* __restrict__ out)
{
    extern __shared__ char sm[];
    const int tid = threadIdx.x;
    const int w = tid >> 5;          // 0..7, owns rows [w*32, w*32+32) of 256
    const int lane = tid & 31;
    const int qp = lane & 3;
    const int qr = lane >> 2;
    const int bid = blockIdx.x;
    const uint32_t smb = smem_u32(sm);

    float* b1s = (float*)(sm + OFF_B1);
    float* b2s = (float*)(sm + OFF_B2);
    float* w3s = (float*)(sm + OFF_W3);

    // ---- prologue: cp.async A tiles + W chunk 0, then scalars ----
    {
        const uint4* asrc = (const uint4*)(g_a + (size_t)bid * 2 * (Tdim * Hdim));
#pragma unroll
        for (int jj = 0; jj < 8; jj++) {
            int i = tid + 256 * jj;                  // 0..2047
            int r = i >> 3, c = i & 7;
            cp_async16(smb + OFF_A1 + r * (SA1 * 2) + c * 16, asrc + i);
        }
        const uint4* w1src = (const uint4*)g_w1h;    // chunk 0
#pragma unroll
        for (int jj = 0; jj < 4; jj++) {
            int i = tid + 256 * jj;                  // 0..1023
            int r = i >> 3, c = i & 7;
            cp_async16(smb + OFF_W1 + r * (SW1 * 2) + c * 16, w1src + i);
        }
#pragma unroll
        for (int jj = 0; jj < 8; jj++) {
            int i = tid + 256 * jj;                  // 0..2047
            int r = i >> 4, c = i & 15;
            cp_async16(smb + OFF_W2 + r * (SW2 * 2) + c * 16,
                       (const uint4*)(g_w2h + r * F1 + c * 8));
        }
        CP_COMMIT();
    }
    for (int i = tid; i < F1; i += 256) b1s[i] = b1[i];
    if (tid < F2) { b2s[tid] = b2[tid]; w3s[tid] = w3[tid]; }

    const int arow_lo = ((lane >> 3) & 1) * 8 + (lane & 7);
    const int acol = ((lane >> 4) & 1) * 8;
    const uint32_t uA1 = smb + OFF_A1 + ((w * 32 + arow_lo) * SA1 + acol) * 2;
    const uint32_t uW1x4 = smb + OFF_W1 + ((lane & 7) * SW1 + (lane >> 3) * 8) * 2;
    const uint32_t uW2x4 = smb + OFF_W2 +
        ((((lane >> 4) * 8 + (lane & 7)) * SW2) + ((lane >> 3) & 1) * 8) * 2;

    float D2[16][2][4];
#pragma unroll
    for (int jj = 0; jj < 16; jj++)
#pragma unroll
        for (int mh = 0; mh < 2; mh++)
#pragma unroll
            for (int p = 0; p < 4; p++) D2[jj][mh][p] = 0.0f;

    uint32_t Ah[2][4][4];
    bool a_loaded = false;

#pragma unroll 1
    for (int ch = 0; ch < 4; ch++) {
        const uint32_t wbuf = (uint32_t)(ch & 1);
        // ---- issue cp.async for chunk ch+1 into the alternate buffers ----
        if (ch + 1 < 4) {
            const uint32_t nb = (uint32_t)((ch + 1) & 1);
            const uint4* w1src = (const uint4*)(g_w1h + (ch + 1) * 128 * Hdim);
#pragma unroll
            for (int jj = 0; jj < 4; jj++) {
                int i = tid + 256 * jj;
                int r = i >> 3, c = i & 7;
                cp_async16(smb + OFF_W1 + nb * 18432 + r * (SW1 * 2) + c * 16, w1src + i);
            }
#pragma unroll
            for (int jj = 0; jj < 8; jj++) {
                int i = tid + 256 * jj;
                int r = i >> 4, c = i & 15;
                cp_async16(smb + OFF_W2 + nb * 34816 + r * (SW2 * 2) + c * 16,
                           (const uint4*)(g_w2h + r * F1 + (ch + 1) * 128 + c * 8));
            }
            CP_COMMIT();
            CP_WAIT(1);
        } else {
            CP_COMMIT();   // empty group keeps the count simple
            CP_WAIT(0);
        }
        __syncthreads();

        // ---- load A1 fragments once (after first arrival) ----
        if (!a_loaded) {
            a_loaded = true;
#pragma unroll
            for (int mh = 0; mh < 2; mh++)
#pragma unroll
                for (int kk = 0; kk < 4; kk++)
                    ldsm_x4(Ah[mh][kk], uA1 + mh * 16 * SA1 * 2 + kk * 32);
        }

        const uint32_t uW1c = uW1x4 + wbuf * 18432;
        const uint32_t uW2c = uW2x4 + wbuf * 34816;

#pragma unroll 1
        for (int s = 0; s < 8; s++) {
            // ---- layer1: batch both n-tiles' W frags ----
            uint32_t bf1[2][8];
#pragma unroll
            for (int jj = 0; jj < 2; jj++) {
                const uint32_t bb = uW1c + (2 * s + jj) * 8 * SW1 * 2;
                ldsm_x4(bf1[jj], bb);
                ldsm_x4(bf1[jj] + 4, bb + 64);
            }
            float D1[2][2][4];
#pragma unroll
            for (int jj = 0; jj < 2; jj++)
#pragma unroll
                for (int mh = 0; mh < 2; mh++)
#pragma unroll
                    for (int p = 0; p < 4; p++) D1[jj][mh][p] = 0.0f;
#pragma unroll
            for (int jj = 0; jj < 2; jj++)
#pragma unroll
                for (int mh = 0; mh < 2; mh++)
#pragma unroll
                    for (int kk = 0; kk < 4; kk++)
                        mma_fp16(D1[jj][mh], Ah[mh][kk], bf1[jj] + 2 * kk);

            // ---- epilogue: relu(D1+b1) -> fp16 A2 fragments ----
            uint32_t ahf[2][4];
#pragma unroll
            for (int jj = 0; jj < 2; jj++) {
                const int nb2 = ch * 128 + (2 * s + jj) * 8 + 2 * qp;
                const float bb0 = b1s[nb2], bb1 = b1s[nb2 + 1];
#pragma unroll
                for (int mh = 0; mh < 2; mh++) {
#pragma unroll
                    for (int pp = 0; pp < 2; pp++) {
                        float v0 = fmaxf(D1[jj][mh][2 * pp] + bb0, 0.0f);
                        float v1 = fmaxf(D1[jj][mh][2 * pp + 1] + bb1, 0.0f);
                        ahf[mh][jj * 2 + pp] = hpack(v0, v1);
                    }
                }
            }
            // ---- layer2: accumulate (k = ch*128 + s*16) ----
#pragma unroll
            for (int j2 = 0; j2 < 16; j2 += 2) {
                uint32_t bf[4];
                ldsm_x4(bf, uW2c + j2 * 8 * SW2 * 2 + s * 32);
                mma_fp16(D2[j2][0], ahf[0], bf);
                mma_fp16(D2[j2][1], ahf[1], bf);
                mma_fp16(D2[j2 + 1][0], ahf[0], bf + 2);
                mma_fp16(D2[j2 + 1][1], ahf[1], bf + 2);
            }
        }
        __syncthreads();   // all reads of wbuf done before it is refilled
    }

    // ---- layer3: out = relu(D2 + b2) . w3 + b3 ----
#pragma unroll
    for (int mh = 0; mh < 2; mh++) {
        float s0 = 0.0f, s1 = 0.0f;
#pragma unroll
        for (int j2 = 0; j2 < 16; j2++) {
            const int n2 = j2 * 8 + 2 * qp;
            const float w30 = w3s[n2], w31 = w3s[n2 + 1];
            const float bb0 = b2s[n2], bb1 = b2s[n2 + 1];
            s0 = fmaf(fmaxf(D2[j2][mh][0] + bb0, 0.0f), w30, s0);
            s0 = fmaf(fmaxf(D2[j2][mh][1] + bb1, 0.0f), w31, s0);
            s1 = fmaf(fmaxf(D2[j2][mh][2] + bb0, 0.0f), w30, s1);
            s1 = fmaf(fmaxf(D2[j2][mh][3] + bb1, 0.0f), w31, s1);
        }
        s0 += __shfl_xor_sync(0xffffffffu, s0, 1);
        s0 += __shfl_xor_sync(0xffffffffu, s0, 2);
        s1 += __shfl_xor_sync(0xffffffffu, s1, 1);
        s1 += __shfl_xor_sync(0xffffffffu, s1, 2);
        if (qp == 0) {
            const float bb = b3[0];
            const int row = bid * 256 + w * 32 + mh * 16 + qr;
            out[row] = s0 + bb;
            out[row + 8] = s1 + bb;
        }
    }
}

// ---------------- launch ----------------
extern "C" void kernel_launch(void* const* d_in, const int* in_sizes, int n_in,
                              void* d_out, int out_size) {
    const float* x    = (const float*)d_in[0];
    const float* W_ih = (const float*)d_in[1];
    const float* W_hh = (const float*)d_in[2];
    const float* b_ih = (const float*)d_in[3];
    const float* b_hh = (const float*)d_in[4];
    const float* w1   = (const float*)d_in[5];
    const float* b1   = (const float*)d_in[6];
    const float* w2   = (const float*)d_in[7];
    const float* b2   = (const float*)d_in[8];
    const float* w3   = (const float*)d_in[9];
    const float* b3   = (const float*)d_in[10];
    float* out = (float*)d_out;

    static int attr_set = 0;
    if (!attr_set) {
        cudaFuncSetAttribute(gru_kernel, cudaFuncAttributeMaxDynamicSharedMemorySize, GSM_TOTAL);
        cudaFuncSetAttribute(mlp_kernel, cudaFuncAttributeMaxDynamicSharedMemorySize, SM_TOTAL);
        attr_set = 1;
    }
    gru_kernel<<<Zdim, 256, GSM_TOTAL>>>(x, W_ih, W_hh, b_ih, b_hh, w1, w2);
    mlp_kernel<<<ZB / 2, 256, SM_TOTAL>>>(b1, b2, b3, w3, out);
}

// round 17
// speedup vs baseline: 1.1891x; 1.0570x over previous
#include <cuda_runtime.h>
#include <cuda_fp16.h>
#include <cstdint>

#define Bdim 32
#define Tdim 128
#define Zdim 100
#define Sdim 6
#define Hdim 64
#define F1 512
#define F2 128
#define ZB (Zdim * Bdim)          // 3200 sequences
#define NROWS (ZB * Tdim)         // 409600

// ---------------- device scratch ----------------
__device__ __align__(16) __half g_a[NROWS * Hdim];   // GRU outputs fp16, row-major tiles
__device__ __align__(16) __half g_w1h[F1 * Hdim];    // w1 [512][64] fp16
__device__ __align__(16) __half g_w2h[F2 * F1];      // w2 [128][512] fp16

// ---------------- helpers ----------------
__device__ __forceinline__ float tanh_mufu(float x) {
    float y; asm("tanh.approx.f32 %0, %1;" : "=f"(y) : "f"(x)); return y;
}
__device__ __forceinline__ float sigmoid_mufu(float v) {
    return fmaf(0.5f, tanh_mufu(0.5f * v), 0.5f);
}
__device__ __forceinline__ uint32_t smem_u32(const void* p) {
    uint32_t a;
    asm("{ .reg .u64 t; cvta.to.shared.u64 t, %1; cvt.u32.u64 %0, t; }" : "=r"(a) : "l"(p));
    return a;
}
__device__ __forceinline__ void ldsm_x4(uint32_t* r, uint32_t addr) {
    asm volatile("ldmatrix.sync.aligned.m8n8.x4.shared.b16 {%0,%1,%2,%3}, [%4];"
                 : "=r"(r[0]), "=r"(r[1]), "=r"(r[2]), "=r"(r[3]) : "r"(addr));
}
__device__ __forceinline__ void ldsm_x2(uint32_t* r, uint32_t addr) {
    asm volatile("ldmatrix.sync.aligned.m8n8.x2.shared.b16 {%0,%1}, [%2];"
                 : "=r"(r[0]), "=r"(r[1]) : "r"(addr));
}
__device__ __forceinline__ void mma_fp16(float* d, const uint32_t* a, const uint32_t* b) {
    asm volatile("mma.sync.aligned.m16n8k16.row.col.f32.f16.f16.f32 "
                 "{%0,%1,%2,%3}, {%4,%5,%6,%7}, {%8,%9}, {%0,%1,%2,%3};"
                 : "+f"(d[0]), "+f"(d[1]), "+f"(d[2]), "+f"(d[3])
                 : "r"(a[0]), "r"(a[1]), "r"(a[2]), "r"(a[3]), "r"(b[0]), "r"(b[1]));
}
__device__ __forceinline__ uint32_t hpack(float x, float y) {
    __half2 t = __floats2half2_rn(x, y);
    return *(uint32_t*)&t;
}
__device__ __forceinline__ uint32_t hpackh(__half x, __half y) {
    return (uint32_t)*(unsigned short*)&x | ((uint32_t)*(unsigned short*)&y << 16);
}
__device__ __forceinline__ void cp_async16(uint32_t dst, const void* src) {
    asm volatile("cp.async.cg.shared.global [%0], [%1], 16;" :: "r"(dst), "l"(src));
}
#define CP_COMMIT() asm volatile("cp.async.commit_group;" ::: "memory")
#define CP_WAIT(n)  asm volatile("cp.async.wait_group %0;" :: "n"(n) : "memory")
#define BAR_GRP(id) asm volatile("bar.sync %0, 128;" :: "r"(id) : "memory")

// ---------------- tensor-core GRU v5: (mt, cg) mapping, NO lo-plane ----------------
// CTA = one zone = 32 sequences. A = h as plain fp16 (h-quantization error
// ~2^-11 enters the gates; measured error budget allows it). Warp (mt,cg)
// computes all 3 gates for h-cols [16cg,16cg+16) of rows [16mt,16mt+16).
#define GOFF_H    0                      // float h[32][66]           8448 B
#define GOFF_WHH  8448                   // half  whh[192][72]       27648 B
#define GOFF_WIH  36096                  // half  wih[192][24]        9216 B
#define GOFF_AH   45312                  // half  ah[32][72]          4608 B
#define GOFF_XA   49920                  // half  xa[2][32][24]       3072 B
#define GSM_TOTAL 52992

__global__ __launch_bounds__(256, 1) void gru_kernel(
    const float* __restrict__ x,
    const float* __restrict__ Wih,
    const float* __restrict__ Whh,
    const float* __restrict__ bihp,
    const float* __restrict__ bhhp,
    const float* __restrict__ w1,
    const float* __restrict__ w2)
{
    extern __shared__ char gsm[];
    float* h_sh  = (float*)(gsm + GOFF_H);
    __half* whh_s = (__half*)(gsm + GOFF_WHH);
    __half* wih_s = (__half*)(gsm + GOFF_WIH);
    __half* ah_s  = (__half*)(gsm + GOFF_AH);
    __half* xa_s  = (__half*)(gsm + GOFF_XA);

    const int tid = threadIdx.x;
    const int w = tid >> 5;
    const int lane = tid & 31;
    const int qp = lane & 3;
    const int qr = lane >> 2;
    const int mt = w >> 2;               // row-half 0/1 (rows mt*16..mt*16+15)
    const int cg = w & 3;                // col-group (h-cols 16cg..16cg+15)
    const int zz = blockIdx.x;           // zone
    const int nseq0 = zz * 32;

    // ---- inlined weight prep for the MLP (grid-stride over 100 CTAs) ----
    {
        const int stride = gridDim.x * blockDim.x;
        for (int i = blockIdx.x * blockDim.x + tid; i < F1 * Hdim; i += stride)
            g_w1h[i] = __float2half(w1[i]);
        for (int i = blockIdx.x * blockDim.x + tid; i < F2 * F1; i += stride)
            g_w2h[i] = __float2half(w2[i]);
    }

    // ---- zero h, wih pad, ah ----
    for (int i = tid; i < 2112; i += 256) ((float*)(gsm + GOFF_H))[i] = 0.0f;
    for (int i = tid; i < 2304; i += 256) ((uint32_t*)(gsm + GOFF_WIH))[i] = 0u;
    for (int i = tid; i < 1152; i += 256) ((uint32_t*)(gsm + GOFF_AH))[i] = 0u;

    // ---- stage W_hh [192][64] -> fp16 stride 72 ----
    for (int i = tid; i < 192 * 64; i += 256)
        whh_s[(i >> 6) * 72 + (i & 63)] = __float2half(Whh[i]);
    __syncthreads();   // wih zero before writing data cols
    // ---- stage W_ih [192][6] -> fp16 stride 24 (cols 6..23 zero) ----
    for (int i = tid; i < 192 * 6; i += 256)
        wih_s[(i / 6) * 24 + (i % 6)] = __float2half(Wih[i]);
    // ---- stage x(t=0) into xa[0] (full-block mapping, pre-loop) ----
    if (tid < 192) {
        int q0 = tid / 6, s0 = tid % 6;
        xa_s[q0 * 24 + s0] = __float2half(x[((q0 * Tdim + 0) * Zdim + zz) * Sdim + s0]);
    }
    __syncthreads();

    // ---- register-resident B fragments: 2 sub-tiles per gate ----
    const uint32_t uWhh = smem_u32(whh_s);
    const uint32_t uWih = smem_u32(wih_s);
    const int Lb = lane & 15;
    uint32_t Bhh[3][2][4][2], Bih[3][2][2];
#pragma unroll
    for (int g = 0; g < 3; g++) {
#pragma unroll
        for (int st = 0; st < 2; st++) {
            const int ng = g * 64 + (cg * 2 + st) * 8;
            uint32_t r4[4];
            ldsm_x4(r4, uWhh + (uint32_t)(ng + (lane & 7)) * 144 + (uint32_t)(lane >> 3) * 16);
            Bhh[g][st][0][0] = r4[0]; Bhh[g][st][0][1] = r4[1];
            Bhh[g][st][1][0] = r4[2]; Bhh[g][st][1][1] = r4[3];
            ldsm_x4(r4, uWhh + (uint32_t)(ng + (lane & 7)) * 144 + (uint32_t)(lane >> 3) * 16 + 64);
            Bhh[g][st][2][0] = r4[0]; Bhh[g][st][2][1] = r4[1];
            Bhh[g][st][3][0] = r4[2]; Bhh[g][st][3][1] = r4[3];
            ldsm_x2(Bih[g][st], uWih + (uint32_t)(ng + (Lb & 7)) * 48 + (uint32_t)(Lb >> 3) * 16);
        }
    }

    // ---- per-lane biases (two col sub-tiles) ----
    float brz[2][2], bz[2][2], bin[2][2], bhn[2][2];
    int cbase[2];
#pragma unroll
    for (int st = 0; st < 2; st++) {
        const int c = cg * 16 + st * 8 + 2 * qp;
        cbase[st] = c;
        brz[st][0] = bihp[c] + bhhp[c];
        brz[st][1] = bihp[c + 1] + bhhp[c + 1];
        bz[st][0]  = bihp[64 + c] + bhhp[64 + c];
        bz[st][1]  = bihp[64 + c + 1] + bhhp[64 + c + 1];
        bin[st][0] = bihp[128 + c];     bin[st][1] = bihp[128 + c + 1];
        bhn[st][0] = bhhp[128 + c];     bhn[st][1] = bhhp[128 + c + 1];
    }

    // ---- per-lane ldmatrix A addressing (own row-half only) ----
    const int arow = mt * 16 + ((lane >> 3) & 1) * 8 + (lane & 7);
    const uint32_t acolb = (uint32_t)((lane >> 4) & 1) * 16;
    const uint32_t uAH = smem_u32(ah_s);
    const uint32_t uXA = smem_u32(xa_s);
    const int barid = mt + 1;

    // group-local x loader mapping (16 seqs per group, 96 of 128 threads)
    const int lt = tid & 127;
    const int qx = mt * 16 + lt / 6, sx = lt % 6;
    const bool xload = (lt < 96);

    for (int t = 0; t < Tdim; t++) {
        const int cur = t & 1;

        // ---- ldsm A fragments (rows of own half; h + x) ----
        uint32_t Ahi[4][4], Ax[4];
#pragma unroll
        for (int kk = 0; kk < 4; kk++)
            ldsm_x4(Ahi[kk], uAH + (uint32_t)arow * 144 + acolb + kk * 32);
        ldsm_x4(Ax, uXA + (uint32_t)cur * 1536 + (uint32_t)arow * 48 + acolb);
        // prefetch x(t+1) (group-local)
        float xvn = 0.0f;
        if (xload && t + 1 < Tdim)
            xvn = x[((qx * Tdim + (t + 1)) * Zdim + zz) * Sdim + sx];
        BAR_GRP(barid);   // group's ldsm reads done before epilogue writes

        float Dh[3][2][4], Dg[3][2][4];
#pragma unroll
        for (int g = 0; g < 3; g++) {
#pragma unroll
            for (int st = 0; st < 2; st++) {
#pragma unroll
                for (int p = 0; p < 4; p++) { Dh[g][st][p] = 0.0f; Dg[g][st][p] = 0.0f; }
#pragma unroll
                for (int kk = 0; kk < 4; kk++) mma_fp16(Dh[g][st], Ahi[kk], Bhh[g][st][kk]);
                mma_fp16(Dg[g][st], Ax, Bih[g][st]);
            }
        }

        // ---- epilogue: gates + h update ----
#pragma unroll
        for (int st = 0; st < 2; st++) {
            const int c = cbase[st];
#pragma unroll
            for (int rr = 0; rr < 2; rr++) {
                const int seqr = mt * 16 + rr * 8 + qr;
                const int i0 = rr * 2, i1 = rr * 2 + 1;
                float r0 = sigmoid_mufu(Dg[0][st][i0] + Dh[0][st][i0] + brz[st][0]);
                float r1 = sigmoid_mufu(Dg[0][st][i1] + Dh[0][st][i1] + brz[st][1]);
                float z0 = sigmoid_mufu(Dg[1][st][i0] + Dh[1][st][i0] + bz[st][0]);
                float z1 = sigmoid_mufu(Dg[1][st][i1] + Dh[1][st][i1] + bz[st][1]);
                float nn0 = tanh_mufu(Dg[2][st][i0] + bin[st][0] + r0 * (Dh[2][st][i0] + bhn[st][0]));
                float nn1 = tanh_mufu(Dg[2][st][i1] + bin[st][1] + r1 * (Dh[2][st][i1] + bhn[st][1]));
                float h0 = h_sh[seqr * 66 + c];
                float h1 = h_sh[seqr * 66 + c + 1];
                float hn0 = nn0 + z0 * (h0 - nn0);
                float hn1 = nn1 + z1 * (h1 - nn1);
                h_sh[seqr * 66 + c]     = hn0;
                h_sh[seqr * 66 + c + 1] = hn1;
                __half hi0 = __float2half(hn0), hi1 = __float2half(hn1);
                uint32_t hp = hpackh(hi0, hi1);
                *(uint32_t*)&ah_s[seqr * 72 + c] = hp;
                *(uint32_t*)&g_a[(size_t)(nseq0 + seqr) * (Tdim * Hdim) + t * Hdim + c] = hp;
            }
        }
        // store x(t+1) into alternate buffer (group-local rows)
        if (xload && t + 1 < Tdim)
            xa_s[(cur ^ 1) * 768 + qx * 24 + sx] = __float2half(xvn);
        BAR_GRP(barid);   // group's writes done before next step's reads
    }
}

// ---------------- tensor-core fused MLP v3 (exact r12/r15): cp.async double-buffered W ----------------
#define SA1 72
#define SW1 72
#define SW2 136
#define OFF_A1 0                   // 256 rows x 144 B = 36864
#define OFF_W1 36864               // 2 bufs x 18432
#define OFF_W2 73728               // 2 bufs x 34816
#define OFF_B1 143360
#define OFF_B2 145408
#define OFF_W3 145920
#define SM_TOTAL 146432

__global__ __launch_bounds__(256, 1) void mlp_kernel(
    const float* __restrict__ b1,
    const float* __restrict__ b2,
    const float* __restrict__ b3,
    const float* __restrict__ w3,
    float* __restrict__ out)
{
    extern __shared__ char sm[];
    const int tid = threadIdx.x;
    const int w = tid >> 5;          // 0..7, owns rows [w*32, w*32+32) of 256
    const int lane = tid & 31;
    const int qp = lane & 3;
    const int qr = lane >> 2;
    const int bid = blockIdx.x;
    const uint32_t smb = smem_u32(sm);

    float* b1s = (float*)(sm + OFF_B1);
    float* b2s = (float*)(sm + OFF_B2);
    float* w3s = (float*)(sm + OFF_W3);

    // ---- prologue: cp.async A tiles + W chunk 0, then scalars ----
    {
        const uint4* asrc = (const uint4*)(g_a + (size_t)bid * 2 * (Tdim * Hdim));
#pragma unroll
        for (int jj = 0; jj < 8; jj++) {
            int i = tid + 256 * jj;                  // 0..2047
            int r = i >> 3, c = i & 7;
            cp_async16(smb + OFF_A1 + r * (SA1 * 2) + c * 16, asrc + i);
        }
        const uint4* w1src = (const uint4*)g_w1h;    // chunk 0
#pragma unroll
        for (int jj = 0; jj < 4; jj++) {
            int i = tid + 256 * jj;                  // 0..1023
            int r = i >> 3, c = i & 7;
            cp_async16(smb + OFF_W1 + r * (SW1 * 2) + c * 16, w1src + i);
        }
#pragma unroll
        for (int jj = 0; jj < 8; jj++) {
            int i = tid + 256 * jj;                  // 0..2047
            int r = i >> 4, c = i & 15;
            cp_async16(smb + OFF_W2 + r * (SW2 * 2) + c * 16,
                       (const uint4*)(g_w2h + r * F1 + c * 8));
        }
        CP_COMMIT();
    }
    for (int i = tid; i < F1; i += 256) b1s[i] = b1[i];
    if (tid < F2) { b2s[tid] = b2[tid]; w3s[tid] = w3[tid]; }

    const int arow_lo = ((lane >> 3) & 1) * 8 + (lane & 7);
    const int acol = ((lane >> 4) & 1) * 8;
    const uint32_t uA1 = smb + OFF_A1 + ((w * 32 + arow_lo) * SA1 + acol) * 2;
    const uint32_t uW1x4 = smb + OFF_W1 + ((lane & 7) * SW1 + (lane >> 3) * 8) * 2;
    const uint32_t uW2x4 = smb + OFF_W2 +
        ((((lane >> 4) * 8 + (lane & 7)) * SW2) + ((lane >> 3) & 1) * 8) * 2;

    float D2[16][2][4];
#pragma unroll
    for (int jj = 0; jj < 16; jj++)
#pragma unroll
        for (int mh = 0; mh < 2; mh++)
#pragma unroll
            for (int p = 0; p < 4; p++) D2[jj][mh][p] = 0.0f;

    uint32_t Ah[2][4][4];
    bool a_loaded = false;

#pragma unroll 1
    for (int ch = 0; ch < 4; ch++) {
        const uint32_t wbuf = (uint32_t)(ch & 1);
        // ---- issue cp.async for chunk ch+1 into the alternate buffers ----
        if (ch + 1 < 4) {
            const uint32_t nb = (uint32_t)((ch + 1) & 1);
            const uint4* w1src = (const uint4*)(g_w1h + (ch + 1) * 128 * Hdim);
#pragma unroll
            for (int jj = 0; jj < 4; jj++) {
                int i = tid + 256 * jj;
                int r = i >> 3, c = i & 7;
                cp_async16(smb + OFF_W1 + nb * 18432 + r * (SW1 * 2) + c * 16, w1src + i);
            }
#pragma unroll
            for (int jj = 0; jj < 8; jj++) {
                int i = tid + 256 * jj;
                int r = i >> 4, c = i & 15;
                cp_async16(smb + OFF_W2 + nb * 34816 + r * (SW2 * 2) + c * 16,
                           (const uint4*)(g_w2h + r * F1 + (ch + 1) * 128 + c * 8));
            }
            CP_COMMIT();
            CP_WAIT(1);
        } else {
            CP_COMMIT();   // empty group keeps the count simple
            CP_WAIT(0);
        }
        __syncthreads();

        // ---- load A1 fragments once (after first arrival) ----
        if (!a_loaded) {
            a_loaded = true;
#pragma unroll
            for (int mh = 0; mh < 2; mh++)
#pragma unroll
                for (int kk = 0; kk < 4; kk++)
                    ldsm_x4(Ah[mh][kk], uA1 + mh * 16 * SA1 * 2 + kk * 32);
        }

        const uint32_t uW1c = uW1x4 + wbuf * 18432;
        const uint32_t uW2c = uW2x4 + wbuf * 34816;

#pragma unroll 1
        for (int s = 0; s < 8; s++) {
            // ---- layer1: batch both n-tiles' W frags ----
            uint32_t bf1[2][8];
#pragma unroll
            for (int jj = 0; jj < 2; jj++) {
                const uint32_t bb = uW1c + (2 * s + jj) * 8 * SW1 * 2;
                ldsm_x4(bf1[jj], bb);
                ldsm_x4(bf1[jj] + 4, bb + 64);
            }
            float D1[2][2][4];
#pragma unroll
            for (int jj = 0; jj < 2; jj++)
#pragma unroll
                for (int mh = 0; mh < 2; mh++)
#pragma unroll
                    for (int p = 0; p < 4; p++) D1[jj][mh][p] = 0.0f;
#pragma unroll
            for (int jj = 0; jj < 2; jj++)
#pragma unroll
                for (int mh = 0; mh < 2; mh++)
#pragma unroll
                    for (int kk = 0; kk < 4; kk++)
                        mma_fp16(D1[jj][mh], Ah[mh][kk], bf1[jj] + 2 * kk);

            // ---- epilogue: relu(D1+b1) -> fp16 A2 fragments ----
            uint32_t ahf[2][4];
#pragma unroll
            for (int jj = 0; jj < 2; jj++) {
                const int nb2 = ch * 128 + (2 * s + jj) * 8 + 2 * qp;
                const float bb0 = b1s[nb2], bb1 = b1s[nb2 + 1];
#pragma unroll
                for (int mh = 0; mh < 2; mh++) {
#pragma unroll
                    for (int pp = 0; pp < 2; pp++) {
                        float v0 = fmaxf(D1[jj][mh][2 * pp] + bb0, 0.0f);
                        float v1 = fmaxf(D1[jj][mh][2 * pp + 1] + bb1, 0.0f);
                        ahf[mh][jj * 2 + pp] = hpack(v0, v1);
                    }
                }
            }
            // ---- layer2: accumulate (k = ch*128 + s*16) ----
#pragma unroll
            for (int j2 = 0; j2 < 16; j2 += 2) {
                uint32_t bf[4];
                ldsm_x4(bf, uW2c + j2 * 8 * SW2 * 2 + s * 32);
                mma_fp16(D2[j2][0], ahf[0], bf);
                mma_fp16(D2[j2][1], ahf[1], bf);
                mma_fp16(D2[j2 + 1][0], ahf[0], bf + 2);
                mma_fp16(D2[j2 + 1][1], ahf[1], bf + 2);
            }
        }
        __syncthreads();   // all reads of wbuf done before it is refilled
    }

    // ---- layer3: out = relu(D2 + b2) . w3 + b3 ----
#pragma unroll
    for (int mh = 0; mh < 2; mh++) {
        float s0 = 0.0f, s1 = 0.0f;
#pragma unroll
        for (int j2 = 0; j2 < 16; j2++) {
            const int n2 = j2 * 8 + 2 * qp;
            const float w30 = w3s[n2], w31 = w3s[n2 + 1];
            const float bb0 = b2s[n2], bb1 = b2s[n2 + 1];
            s0 = fmaf(fmaxf(D2[j2][mh][0] + bb0, 0.0f), w30, s0);
            s0 = fmaf(fmaxf(D2[j2][mh][1] + bb1, 0.0f), w31, s0);
            s1 = fmaf(fmaxf(D2[j2][mh][2] + bb0, 0.0f), w30, s1);
            s1 = fmaf(fmaxf(D2[j2][mh][3] + bb1, 0.0f), w31, s1);
        }
        s0 += __shfl_xor_sync(0xffffffffu, s0, 1);
        s0 += __shfl_xor_sync(0xffffffffu, s0, 2);
        s1 += __shfl_xor_sync(0xffffffffu, s1, 1);
        s1 += __shfl_xor_sync(0xffffffffu, s1, 2);
        if (qp == 0) {
            const float bb = b3[0];
            const int row = bid * 256 + w * 32 + mh * 16 + qr;
            out[row] = s0 + bb;
            out[row + 8] = s1 + bb;
        }
    }
}

// ---------------- launch ----------------
extern "C" void kernel_launch(void* const* d_in, const int* in_sizes, int n_in,
                              void* d_out, int out_size) {
    const float* x    = (const float*)d_in[0];
    const float* W_ih = (const float*)d_in[1];
    const float* W_hh = (const float*)d_in[2];
    const float* b_ih = (const float*)d_in[3];
    const float* b_hh = (const float*)d_in[4];
    const float* w1   = (const float*)d_in[5];
    const float* b1   = (const float*)d_in[6];
    const float* w2   = (const float*)d_in[7];
    const float* b2   = (const float*)d_in[8];
    const float* w3   = (const float*)d_in[9];
    const float* b3   = (const float*)d_in[10];
    float* out = (float*)d_out;

    static int attr_set = 0;
    if (!attr_set) {
        cudaFuncSetAttribute(gru_kernel, cudaFuncAttributeMaxDynamicSharedMemorySize, GSM_TOTAL);
        cudaFuncSetAttribute(mlp_kernel, cudaFuncAttributeMaxDynamicSharedMemorySize, SM_TOTAL);
        attr_set = 1;
    }
    gru_kernel<<<Zdim, 256, GSM_TOTAL>>>(x, W_ih, W_hh, b_ih, b_hh, w1, w2);
    mlp_kernel<<<ZB / 2, 256, SM_TOTAL>>>(b1, b2, b3, w3, out);
}